// round 15
// baseline (speedup 1.0000x reference)
#include <cuda_runtime.h>
#include <cuda_bf16.h>
#include <cstdint>

#define BB   8
#define KKc  256
#define DDc  256
#define TTc  2048
#define NHH  4
#define HDD  64
#define NV   320        // extended v width: 256 v | 48 conv | 1 dur | 15 pad

typedef unsigned long long ull;

// ---------------- scratch (__device__ globals) --------------------------------
__device__ __align__(16) float g_v2[(size_t)BB*KKc*NV];
__device__ __align__(16) float g_Wcat[DDc*NV];
__device__ __align__(16) float g_bcat[NV];
__device__ __align__(16) float g_baseW[BB*KKc*16];   // row layout [b][k][16]
__device__ __align__(16) float g_baseC[BB*KKc*2];
__device__ __align__(16) float g_ein[(size_t)BB*TTc*8];
__device__ __align__(16) float g_oL[(size_t)BB*TTc*DDc];
__device__ __align__(16) float g_M[8*DDc];
__device__ __align__(16) float g_cbias[DDc];
__device__ __align__(16) float g_dF[BB*KKc];
__device__ __align__(16) float g_attnF[(size_t)BB*NHH*TTc*KKc];

// ---------------- constant-bank weights for k_mlp -----------------------------
__constant__ __align__(16) float c_sw1A[32];
__constant__ __align__(16) float c_sw2[16*16];
__constant__ __align__(16) float c_sw2b[16];
__constant__ __align__(16) float c_we[16*4];
__constant__ __align__(16) float c_web[4];
__constant__ __align__(16) float c_sc1[4];
__constant__ __align__(16) float c_sc2[4];
__constant__ __align__(16) float c_sc2b[2];

// ---------------- f32x2 helpers ------------------------------------------------
__device__ __forceinline__ ull pack2(float x, float y){
    ull r; asm("mov.b64 %0, {%1,%2};" : "=l"(r) : "f"(x), "f"(y)); return r;
}
__device__ __forceinline__ ull fma2(ull a, ull b, ull c){
    ull d; asm("fma.rn.f32x2 %0, %1, %2, %3;" : "=l"(d) : "l"(a), "l"(b), "l"(c));
    return d;
}
__device__ __forceinline__ float2 unpack2(ull v){
    float x, y; asm("mov.b64 {%0,%1}, %2;" : "=f"(x), "=f"(y) : "l"(v));
    return make_float2(x, y);
}
__device__ __forceinline__ ull dtou(double d){ return __double_as_longlong(d); }

union F4 { float4 v; ull u[2]; float f[4]; uint32_t w[4]; };

__device__ __forceinline__ float siluf(float x){
    float t, hx = 0.5f * x;
    asm("tanh.approx.f32 %0, %1;" : "=f"(t) : "f"(hx));
    return fmaf(hx, t, hx);
}

// ---------------- warp-MMA helpers (baseline PTX, compute_103-safe) ------------
__device__ __forceinline__ uint32_t smem_u32(const void* p){
    uint32_t a;
    asm("{ .reg .u64 t; cvta.to.shared.u64 t, %1; cvt.u32.u64 %0, t; }"
        : "=r"(a) : "l"(p));
    return a;
}
__device__ __forceinline__ uint32_t swz(uint32_t x){ return x ^ ((x >> 3) & 0x70); }

#define LDSM4(r, addr) \
    asm volatile("ldmatrix.sync.aligned.m8n8.x4.shared.b16 {%0,%1,%2,%3}, [%4];" \
        : "=r"((r)[0]), "=r"((r)[1]), "=r"((r)[2]), "=r"((r)[3]) : "r"(addr))

#define LDSM4T(r, addr) \
    asm volatile("ldmatrix.sync.aligned.m8n8.x4.trans.shared.b16 {%0,%1,%2,%3}, [%4];" \
        : "=r"((r)[0]), "=r"((r)[1]), "=r"((r)[2]), "=r"((r)[3]) : "r"(addr))

#define MMA_BF16(c, a, b0, b1) \
    asm volatile("mma.sync.aligned.m16n8k16.row.col.f32.bf16.bf16.f32 " \
        "{%0,%1,%2,%3}, {%4,%5,%6,%7}, {%8,%9}, {%0,%1,%2,%3};" \
        : "+f"((c)[0]), "+f"((c)[1]), "+f"((c)[2]), "+f"((c)[3]) \
        : "r"((a)[0]), "r"((a)[1]), "r"((a)[2]), "r"((a)[3]), "r"(b0), "r"(b1))

__device__ __forceinline__ void cvt_hilo(float x, float y, uint32_t& hi, uint32_t& lo){
    asm("cvt.rn.bf16x2.f32 %0, %1, %2;" : "=r"(hi) : "f"(y), "f"(x));
    float fx = __uint_as_float(hi << 16), fy = __uint_as_float(hi & 0xffff0000u);
    asm("cvt.rn.bf16x2.f32 %0, %1, %2;" : "=r"(lo) : "f"(y - fy), "f"(x - fx));
}

// SMEM layout (dynamic)
#define OFF_EPI 0
#define OFF_AHI 2560
#define OFF_ALO (OFF_AHI + 16384)
#define OFF_BHI (OFF_ALO + 16384)
#define OFF_BLO (OFF_BHI + 8192)
#define MMA_SMEM (OFF_BLO + 8192)     // 51712

// ---------------- mma_gemm (R11 measured-best, non-pipelined, FROZEN) ----------
template<int MODE>
__global__ void __launch_bounds__(256) mma_gemm(
        const float* __restrict__ Aall, const float* __restrict__ Ball,
        const float* __restrict__ biasv, float* __restrict__ Call){
    extern __shared__ char smem[];
    uint32_t sb = smem_u32(smem);
    int tid = threadIdx.x, wid = tid >> 5, lane = tid & 31;
    int warpM = wid >> 1, warpN = wid & 1;
    int row0 = blockIdx.x * 128;

    const float* A; const float* Bsrc; float* C;
    int lda, ldb, ldc, n0;
    if (MODE == 0){
        A = Aall; lda = DDc; Bsrc = Ball; ldb = NV;
        C = Call; ldc = NV; n0 = blockIdx.y * 64;
    } else if (MODE == 1){
        int z = blockIdx.z, b = z >> 2, h = z & 3;
        A = Aall + (size_t)z * TTc * KKc; lda = KKc;
        Bsrc = Ball + (size_t)b * KKc * NV + h * HDD; ldb = NV;
        C = Call + (size_t)b * TTc * DDc + h * HDD; ldc = DDc; n0 = 0;
    } else {
        A = Aall; lda = DDc; Bsrc = Ball; ldb = DDc;
        C = Call; ldc = DDc; n0 = blockIdx.y * 64;
    }

    float* sEpi = (float*)(smem + OFF_EPI);
    if (MODE == 0){
        if (tid < 64) sEpi[tid] = biasv[n0 + tid];
    }
    if (MODE == 2){
        sEpi[tid]       = g_M[(tid >> 6)*DDc + n0 + (tid & 63)];
        sEpi[256 + tid] = g_M[((256 + tid) >> 6)*DDc + n0 + (tid & 63)];
        if (tid < 64) sEpi[512 + tid] = g_cbias[n0 + tid];
    }

    float acc[2][4][4];
    #pragma unroll
    for (int mi = 0; mi < 2; mi++)
        #pragma unroll
        for (int ni = 0; ni < 4; ni++)
            #pragma unroll
            for (int q = 0; q < 4; q++) acc[mi][ni][q] = 0.f;

    int lr = lane & 7, lm = (lane >> 3) & 1, lh = lane >> 4;
    int arow = warpM*32 + lm*8 + lr;
    int btrow = lane & 15;
    int btcol = (lane >> 4) * 8;

    for (int kc = 0; kc < 4; kc++){
        int k0 = kc * 64;
        #pragma unroll
        for (int i = 0; i < 8; i++){
            int idx = i * 256 + tid;
            int r = idx >> 4, c4 = (idx & 15) * 4;
            float4 v = *(const float4*)&A[(size_t)(row0 + r)*lda + k0 + c4];
            uint32_t h0, l0, h1, l1;
            cvt_hilo(v.x, v.y, h0, l0);
            cvt_hilo(v.z, v.w, h1, l1);
            uint32_t so = swz((uint32_t)(r*128 + c4*2));
            *(uint2*)(smem + OFF_AHI + so) = make_uint2(h0, h1);
            *(uint2*)(smem + OFF_ALO + so) = make_uint2(l0, l1);
        }
        #pragma unroll
        for (int i = 0; i < 4; i++){
            int idx = i * 256 + tid;
            int k = idx >> 4, n4 = (idx & 15) * 4;
            float4 v = *(const float4*)&Bsrc[(size_t)(k0 + k)*ldb + n0 + n4];
            uint32_t h0, l0, h1, l1;
            cvt_hilo(v.x, v.y, h0, l0);
            cvt_hilo(v.z, v.w, h1, l1);
            uint32_t so = swz((uint32_t)(k*128 + n4*2));
            *(uint2*)(smem + OFF_BHI + so) = make_uint2(h0, h1);
            *(uint2*)(smem + OFF_BLO + so) = make_uint2(l0, l1);
        }
        __syncthreads();

        #pragma unroll
        for (int kk = 0; kk < 4; kk++){
            int acol = (kk*16 + lh*8) * 2;
            uint32_t ah[2][4], al[2][4], bh[2][4], bl[2][4];
            #pragma unroll
            for (int mi = 0; mi < 2; mi++){
                uint32_t off = swz((uint32_t)((arow + mi*16)*128 + acol));
                LDSM4(ah[mi], sb + OFF_AHI + off);
                LDSM4(al[mi], sb + OFF_ALO + off);
            }
            #pragma unroll
            for (int p = 0; p < 2; p++){
                uint32_t off = swz((uint32_t)((kk*16 + btrow)*128 +
                                              (warpN*32 + p*16 + btcol)*2));
                LDSM4T(bh[p], sb + OFF_BHI + off);
                LDSM4T(bl[p], sb + OFF_BLO + off);
            }
            #pragma unroll
            for (int mi = 0; mi < 2; mi++)
                #pragma unroll
                for (int ni = 0; ni < 4; ni++){
                    int p = ni >> 1, o = (ni & 1) * 2;
                    MMA_BF16(acc[mi][ni], ah[mi], bh[p][o], bh[p][o+1]);
                    MMA_BF16(acc[mi][ni], ah[mi], bl[p][o], bl[p][o+1]);
                    MMA_BF16(acc[mi][ni], al[mi], bh[p][o], bh[p][o+1]);
                }
        }
        __syncthreads();
    }

    int gid = lane >> 2, tig = lane & 3;
    #pragma unroll
    for (int mi = 0; mi < 2; mi++){
        int r0g = row0 + warpM*32 + mi*16 + gid;
        int r1g = r0g + 8;
        float e0[8], e1[8];
        if (MODE == 2){
            const float* p0 = g_ein + (size_t)r0g * 8;
            const float* p1 = g_ein + (size_t)r1g * 8;
            *(float4*)&e0[0] = *(const float4*)p0;
            *(float4*)&e0[4] = *(const float4*)(p0 + 4);
            *(float4*)&e1[0] = *(const float4*)p1;
            *(float4*)&e1[4] = *(const float4*)(p1 + 4);
        }
        #pragma unroll
        for (int ni = 0; ni < 4; ni++){
            int cl = warpN*32 + ni*8 + tig*2;
            float v0 = acc[mi][ni][0], v1 = acc[mi][ni][1];
            float v2a = acc[mi][ni][2], v3 = acc[mi][ni][3];
            if (MODE == 0){
                float b0 = sEpi[cl], b1 = sEpi[cl+1];
                v0 += b0; v1 += b1; v2a += b0; v3 += b1;
            }
            if (MODE == 2){
                float b0 = sEpi[512 + cl], b1 = sEpi[512 + cl + 1];
                v0 += b0; v1 += b1; v2a += b0; v3 += b1;
                #pragma unroll
                for (int q = 0; q < 8; q++){
                    float m0 = sEpi[q*64 + cl], m1 = sEpi[q*64 + cl + 1];
                    v0  = fmaf(e0[q], m0, v0);   v1  = fmaf(e0[q], m1, v1);
                    v2a = fmaf(e1[q], m0, v2a);  v3  = fmaf(e1[q], m1, v3);
                }
            }
            *(float2*)&C[(size_t)r0g*ldc + n0 + cl] = make_float2(v0, v1);
            *(float2*)&C[(size_t)r1g*ldc + n0 + cl] = make_float2(v2a, v3);
        }
    }
}

// ---------------- K_pre: merged prep ------------------------------------------
__global__ void k_pre(const float* __restrict__ ceW, const float* __restrict__ ceb,
                      const float* __restrict__ W3,  const float* __restrict__ b2,
                      const float* __restrict__ b3,  const float* __restrict__ W1,
                      const float* __restrict__ b1,  const float* __restrict__ wck,
                      const float* __restrict__ cck, const float* __restrict__ Wd,
                      const float* __restrict__ bd){
    int blk = blockIdx.x;
    if (blk < 9){
        int n = threadIdx.x;
        if (n >= 256) return;
        if (blk < 8){
            int h = blk >> 1, p = blk & 1;
            float s = 0.f;
            #pragma unroll 16
            for (int d = 0; d < HDD; d++)
                s = fmaf(ceW[p*HDD + d], W3[(size_t)(h*HDD + d)*DDc + n], s);
            g_M[blk*DDc + n] = s;
        } else {
            float s = b2[n] + b3[n];
            for (int h = 0; h < 4; h++)
                #pragma unroll 16
                for (int d = 0; d < HDD; d++)
                    s = fmaf(ceb[d], W3[(size_t)(h*HDD + d)*DDc + n], s);
            g_cbias[n] = s;
        }
        return;
    }
    int d = blk - 9;
    int c = threadIdx.x;
    const float* vec = (d < DDc) ? (W1 + (size_t)d*DDc) : b1;
    float out = 0.f;
    if (c < 256){
        out = vec[c];
    } else if (c < 304){
        int i = c - 256;
        const float* kern = (i < 24) ? wck : cck;
        int ii = (i < 24) ? i : i - 24;
        int f = ii / 3, r = ii % 3;
        float s = 0.f;
        for (int dd = 0; dd < DDc; dd++)
            s = fmaf(vec[dd], kern[(f*DDc + dd)*3 + r], s);
        out = s;
    } else if (c == 304){
        out = (d < DDc) ? Wd[d] : bd[0];
    }
    if (d < DDc) g_Wcat[(size_t)d*NV + c] = out;
    else         g_bcat[c] = out;
}

// ---------------- K_durcomb: cumsum + combine + LN + fold ---------------------
__global__ void k_durcomb(float* __restrict__ out_d,
                          const float* __restrict__ wcb, const float* __restrict__ wg,
                          const float* __restrict__ wbe, const float* __restrict__ ccb,
                          const float* __restrict__ cg,  const float* __restrict__ cbe,
                          const float* __restrict__ sw1, const float* __restrict__ sw1b,
                          const float* __restrict__ sc1, const float* __restrict__ sc1b){
    extern __shared__ float sU[];            // [256][52]
    __shared__ float ws[8];
    int b = blockIdx.x, k = threadIdx.x;
    int warp = k >> 5, lane = k & 31;

    float dl = fmaxf(g_v2[((size_t)b*KKc + k)*NV + 304], 0.f);
    float dv = fmaxf(__expf(dl) - 1.0f, 1e-12f);
    out_d[b*KKc + k] = dv;
    float x = dv;
    #pragma unroll
    for (int o = 1; o < 32; o <<= 1){
        float y = __shfl_up_sync(0xffffffffu, x, o);
        if (lane >= o) x += y;
    }
    if (lane == 31) ws[warp] = x;
    __syncthreads();
    if (warp == 0 && lane < 8){
        float y = ws[lane];
        #pragma unroll
        for (int o = 1; o < 8; o <<= 1){
            float z = __shfl_up_sync(0xffu, y, o, 8);
            if (lane >= o) y += z;
        }
        ws[lane] = y;
    }
    __syncthreads();
    float ev = x + (warp ? ws[warp-1] : 0.f);
    float sv = ev - dv;

    {
        const float* src = g_v2 + ((size_t)b*KKc + k)*NV + 256;
        float* row = sU + k*52;
        #pragma unroll
        for (int q = 0; q < 12; q++)
            *(float4*)&row[q*4] = *(const float4*)&src[q*4];
    }
    __syncthreads();

    const float* rm = sU + (k-1)*52;
    const float* rc = sU + k*52;
    const float* rp = sU + (k+1)*52;
    float wy[8], cy[8];
    #pragma unroll
    for (int f = 0; f < 8; f++){
        wy[f] = wcb[f] + rc[f*3 + 1];
        cy[f] = ccb[f] + rc[24 + f*3 + 1];
    }
    if (k > 0){
        #pragma unroll
        for (int f = 0; f < 8; f++){
            wy[f] += rm[f*3 + 0];
            cy[f] += rm[24 + f*3 + 0];
        }
    }
    if (k < KKc-1){
        #pragma unroll
        for (int f = 0; f < 8; f++){
            wy[f] += rp[f*3 + 2];
            cy[f] += rp[24 + f*3 + 2];
        }
    }
    float muw = 0.f, muc = 0.f;
    #pragma unroll
    for (int f = 0; f < 8; f++){ muw += wy[f]; muc += cy[f]; }
    muw *= 0.125f; muc *= 0.125f;
    float vw = 0.f, vc = 0.f;
    #pragma unroll
    for (int f = 0; f < 8; f++){
        float a = wy[f]-muw; vw += a*a;
        float c = cy[f]-muc; vc += c*c;
    }
    vw *= 0.125f; vc *= 0.125f;
    float rw = rsqrtf(vw + 1e-5f), rcv = rsqrtf(vc + 1e-5f);
    float wf[8], cf[8];
    #pragma unroll
    for (int f = 0; f < 8; f++){
        wf[f] = siluf((wy[f]-muw)*rw*wg[f] + wbe[f]);
        cf[f] = siluf((cy[f]-muc)*rcv*cg[f] + cbe[f]);
    }
    float* bw = g_baseW + ((size_t)b*KKc + k)*16;
    #pragma unroll
    for (int j = 0; j < 16; j++){
        float s2 = sw1b[j];
        #pragma unroll
        for (int f = 0; f < 8; f++) s2 = fmaf(wf[f], sw1[(2+f)*16 + j], s2);
        s2 = fmaf(-sv, sw1[j], fmaf(ev, sw1[16 + j], s2));
        bw[j] = s2;
    }
    float* bc = g_baseC + ((size_t)b*KKc + k)*2;
    #pragma unroll
    for (int j = 0; j < 2; j++){
        float s2 = sc1b[j];
        #pragma unroll
        for (int f = 0; f < 8; f++) s2 = fmaf(cf[f], sc1[(2+f)*2 + j], s2);
        s2 = fmaf(-sv, sc1[j], fmaf(ev, sc1[2 + j], s2));
        bc[j] = s2;
    }
}

// ---------------- K4: warp-per-t MLP, smem-staged bases, occ=3 ----------------
// R14 structure; gw2 moved from 16 registers to shared (lane-uniform LDS
// broadcasts) to fit the 3-blocks/SM register budget.
__global__ void __launch_bounds__(256, 3) k_mlp(float* __restrict__ attn_out){
    __shared__ __align__(16) float sW[4*KKc*4];    // 16 KB, [q][k][4]
    __shared__ __align__(16) float sC[KKc*2];      // 2 KB,  [k][2]
    __shared__ __align__(16) float sG[16];         // gW = A0 - A1
    int tid = threadIdx.x, b = blockIdx.y;

    {
        const float* src = g_baseW + ((size_t)b*KKc + tid)*16;
        #pragma unroll
        for (int q = 0; q < 4; q++){
            float4 v = *(const float4*)(src + q*4);
            *(float4*)&sW[(q*KKc + tid)*4] = v;
        }
        *(float2*)&sC[tid*2] = *(const float2*)(g_baseC + ((size_t)b*KKc + tid)*2);
        if (tid < 16) sG[tid] = c_sw1A[tid] - c_sw1A[16 + tid];
    }
    __syncthreads();

    int warp = tid >> 5, lane = tid & 31;
    int t = (blockIdx.x << 3) + warp;
    float ts = (float)(t + 1);
    ull ts2 = pack2(ts, ts);

    float cd0 = c_sc1[0] - c_sc1[2], cd1 = c_sc1[1] - c_sc1[3];

    const double* w2d = (const double*)c_sw2;
    const double* b2d = (const double*)c_sw2b;
    const double* wed  = (const double*)c_we;
    const double* webd = (const double*)c_web;
    const ull* sGd = (const ull*)sG;

    float lg[8][4];
    float hcv0[8], hcv1[8];

    #pragma unroll
    for (int j = 0; j < 8; j++){
        int kk = lane + 32*j;                  // strided ownership
        F4 w0 = *(const F4*)&sW[(0*KKc + kk)*4];
        F4 w1 = *(const F4*)&sW[(1*KKc + kk)*4];
        F4 w2 = *(const F4*)&sW[(2*KKc + kk)*4];
        F4 w3 = *(const F4*)&sW[(3*KKc + kk)*4];
        ull bw[8] = {w0.u[0], w0.u[1], w1.u[0], w1.u[1],
                     w2.u[0], w2.u[1], w3.u[0], w3.u[1]};
        float h1[16];
        #pragma unroll
        for (int q = 0; q < 8; q++){
            ull tv = fma2(ts2, sGd[q], bw[q]);     // lane-uniform LDS.64 broadcast
            float2 f = unpack2(tv);
            h1[2*q]   = siluf(f.x);
            h1[2*q+1] = siluf(f.y);
        }
        ull acc2[8];
        #pragma unroll
        for (int q = 0; q < 8; q++) acc2[q] = dtou(b2d[q]);
        #pragma unroll
        for (int j1 = 0; j1 < 16; j1++){
            ull a2 = pack2(h1[j1], h1[j1]);
            #pragma unroll
            for (int q = 0; q < 8; q++)
                acc2[q] = fma2(a2, dtou(w2d[j1*8 + q]), acc2[q]);
        }
        ull lg2[2] = {dtou(webd[0]), dtou(webd[1])};
        #pragma unroll
        for (int j2 = 0; j2 < 8; j2++){
            float2 f = unpack2(acc2[j2]);
            float ha = siluf(f.x), hb = siluf(f.y);
            int jj = 2*j2;
            ull ha2 = pack2(ha, ha), hb2 = pack2(hb, hb);
            lg2[0] = fma2(ha2, dtou(wed[jj*2+0]), lg2[0]);
            lg2[1] = fma2(ha2, dtou(wed[jj*2+1]), lg2[1]);
            lg2[0] = fma2(hb2, dtou(wed[(jj+1)*2+0]), lg2[0]);
            lg2[1] = fma2(hb2, dtou(wed[(jj+1)*2+1]), lg2[1]);
        }
        { float2 f = unpack2(lg2[0]); lg[j][0] = f.x; lg[j][1] = f.y; }
        { float2 f = unpack2(lg2[1]); lg[j][2] = f.x; lg[j][3] = f.y; }

        float2 bc2 = *(const float2*)&sC[kk*2];
        float c10 = siluf(fmaf(ts, cd0, bc2.x));
        float c11 = siluf(fmaf(ts, cd1, bc2.y));
        hcv0[j] = siluf(fmaf(c10, c_sc2[0], fmaf(c11, c_sc2[2], c_sc2b[0])));
        hcv1[j] = siluf(fmaf(c10, c_sc2[1], fmaf(c11, c_sc2[3], c_sc2b[1])));
    }

    float gm[4];
    #pragma unroll
    for (int h = 0; h < 4; h++){
        float m = lg[0][h];
        #pragma unroll
        for (int j = 1; j < 8; j++) m = fmaxf(m, lg[j][h]);
        #pragma unroll
        for (int o = 16; o > 0; o >>= 1)
            m = fmaxf(m, __shfl_xor_sync(0xffffffffu, m, o));
        gm[h] = m;
    }
    float inv[4];
    #pragma unroll
    for (int h = 0; h < 4; h++){
        float s = 0.f;
        #pragma unroll
        for (int j = 0; j < 8; j++){
            lg[j][h] = __expf(lg[j][h] - gm[h]);
            s += lg[j][h];
        }
        #pragma unroll
        for (int o = 16; o > 0; o >>= 1)
            s += __shfl_xor_sync(0xffffffffu, s, o);
        inv[h] = __fdividef(1.f, s);
    }

    float e8[8];
    #pragma unroll
    for (int i = 0; i < 8; i++) e8[i] = 0.f;
    #pragma unroll
    for (int h = 0; h < 4; h++){
        float* dst = attn_out + ((size_t)(b*4 + h)*TTc + t)*KKc + lane;
        #pragma unroll
        for (int j = 0; j < 8; j++){
            float a = lg[j][h] * inv[h];
            e8[h*2]   = fmaf(a, hcv0[j], e8[h*2]);
            e8[h*2+1] = fmaf(a, hcv1[j], e8[h*2+1]);
            dst[32*j] = a;
        }
    }
    #pragma unroll
    for (int i = 0; i < 8; i++){
        #pragma unroll
        for (int o = 16; o > 0; o >>= 1)
            e8[i] += __shfl_xor_sync(0xffffffffu, e8[i], o);
    }
    if (lane == 0){
        float* dst = g_ein + ((size_t)b*TTc + t)*8;
        *(float4*)dst       = *(float4*)&e8[0];
        *(float4*)(dst + 4) = *(float4*)&e8[4];
    }
}

// ---------------- launch ------------------------------------------------------
extern "C" void kernel_launch(void* const* d_in, const int* in_sizes, int n_in,
                              void* d_out, int out_size){
    const float* phs  = (const float*)d_in[0];
    const float* Wd   = (const float*)d_in[4];
    const float* bd   = (const float*)d_in[5];
    const float* W1   = (const float*)d_in[6];
    const float* b1   = (const float*)d_in[7];
    const float* W2   = (const float*)d_in[8];
    const float* b2   = (const float*)d_in[9];
    const float* W3   = (const float*)d_in[10];
    const float* b3   = (const float*)d_in[11];
    const float* wck  = (const float*)d_in[12];
    const float* wcb  = (const float*)d_in[13];
    const float* wlg  = (const float*)d_in[14];
    const float* wlb  = (const float*)d_in[15];
    const float* cck  = (const float*)d_in[16];
    const float* ccb  = (const float*)d_in[17];
    const float* clg  = (const float*)d_in[18];
    const float* clb  = (const float*)d_in[19];
    const float* sw1  = (const float*)d_in[20];
    const float* sw1b = (const float*)d_in[21];
    const float* sw2  = (const float*)d_in[22];
    const float* sw2b = (const float*)d_in[23];
    const float* sc1  = (const float*)d_in[24];
    const float* sc1b = (const float*)d_in[25];
    const float* sc2  = (const float*)d_in[26];
    const float* sc2b = (const float*)d_in[27];
    const float* weW  = (const float*)d_in[28];
    const float* web  = (const float*)d_in[29];
    const float* ceW  = (const float*)d_in[30];
    const float* ceb  = (const float*)d_in[31];
    (void)in_sizes; (void)n_in;

    float* outp = (float*)d_out;
    const size_t nOut  = (size_t)BB*TTc*DDc;
    const size_t nD    = (size_t)BB*KKc;
    const size_t nAttn = (size_t)BB*NHH*TTc*KKc;
    bool full = ((size_t)out_size >= nOut + nD + nAttn);

    float *vP, *oLP, *attnP, *dP, *bcatP, *WcatP;
    cudaGetSymbolAddress((void**)&vP,    g_v2);
    cudaGetSymbolAddress((void**)&oLP,   g_oL);
    cudaGetSymbolAddress((void**)&bcatP, g_bcat);
    cudaGetSymbolAddress((void**)&WcatP, g_Wcat);
    if (full){
        dP    = outp + nOut;
        attnP = outp + nOut + nD;
    } else {
        cudaGetSymbolAddress((void**)&dP,    g_dF);
        cudaGetSymbolAddress((void**)&attnP, g_attnF);
    }

    cudaMemcpyToSymbolAsync(c_sw1A, sw1,  32*sizeof(float), 0, cudaMemcpyDeviceToDevice);
    cudaMemcpyToSymbolAsync(c_sw2,  sw2, 256*sizeof(float), 0, cudaMemcpyDeviceToDevice);
    cudaMemcpyToSymbolAsync(c_sw2b, sw2b, 16*sizeof(float), 0, cudaMemcpyDeviceToDevice);
    cudaMemcpyToSymbolAsync(c_we,   weW,  64*sizeof(float), 0, cudaMemcpyDeviceToDevice);
    cudaMemcpyToSymbolAsync(c_web,  web,   4*sizeof(float), 0, cudaMemcpyDeviceToDevice);
    cudaMemcpyToSymbolAsync(c_sc1,  sc1,   4*sizeof(float), 0, cudaMemcpyDeviceToDevice);
    cudaMemcpyToSymbolAsync(c_sc2,  sc2,   4*sizeof(float), 0, cudaMemcpyDeviceToDevice);
    cudaMemcpyToSymbolAsync(c_sc2b, sc2b,  2*sizeof(float), 0, cudaMemcpyDeviceToDevice);

    cudaFuncSetAttribute(mma_gemm<0>, cudaFuncAttributeMaxDynamicSharedMemorySize, MMA_SMEM);
    cudaFuncSetAttribute(mma_gemm<1>, cudaFuncAttributeMaxDynamicSharedMemorySize, MMA_SMEM);
    cudaFuncSetAttribute(mma_gemm<2>, cudaFuncAttributeMaxDynamicSharedMemorySize, MMA_SMEM);
    cudaFuncSetAttribute(k_durcomb, cudaFuncAttributeMaxDynamicSharedMemorySize,
                         KKc*52*(int)sizeof(float));

    k_pre<<<266, NV>>>(ceW, ceb, W3, b2, b3, W1, b1, wck, cck, Wd, bd);
    mma_gemm<0><<<dim3(BB*KKc/128, NV/64), 256, MMA_SMEM>>>(phs, WcatP, bcatP, vP);
    k_durcomb<<<BB, KKc, KKc*52*sizeof(float)>>>(dP, wcb, wlg, wlb, ccb, clg, clb,
                                                 sw1, sw1b, sc1, sc1b);
    k_mlp<<<dim3(TTc/8, BB), 256>>>(attnP);
    mma_gemm<1><<<dim3(TTc/128, 1, BB*NHH), 256, MMA_SMEM>>>(attnP, vP, nullptr, oLP);
    mma_gemm<2><<<dim3(BB*TTc/128, DDc/64), 256, MMA_SMEM>>>(oLP, W2, nullptr, outp);
}

// round 16
// speedup vs baseline: 1.0572x; 1.0572x over previous
#include <cuda_runtime.h>
#include <cuda_bf16.h>
#include <cstdint>

#define BB   8
#define KKc  256
#define DDc  256
#define TTc  2048
#define NHH  4
#define HDD  64
#define NV   320        // extended v width: 256 v | 48 conv | 1 dur | 15 pad

typedef unsigned long long ull;

// ---------------- scratch (__device__ globals) --------------------------------
__device__ __align__(16) float g_v2[(size_t)BB*KKc*NV];
__device__ __align__(16) float g_Wcat[DDc*NV];
__device__ __align__(16) float g_bcat[NV];
__device__ __align__(16) float g_baseW[BB*KKc*16];   // row layout [b][k][16]
__device__ __align__(16) float g_baseC[BB*KKc*2];
__device__ __align__(16) float g_ein[(size_t)BB*TTc*8];
__device__ __align__(16) float g_oL[(size_t)BB*TTc*DDc];
__device__ __align__(16) float g_M[8*DDc];
__device__ __align__(16) float g_cbias[DDc];
__device__ __align__(16) float g_cpack[384];
__device__ __align__(16) float g_dF[BB*KKc];
__device__ __align__(16) float g_attnF[(size_t)BB*NHH*TTc*KKc];

// ---------------- packed constant bank (single memcpy) -------------------------
// layout: [0:32) sw1A | [32:288) sw2 | [288:304) sw2b | [304:368) we
//         [368:372) web | [372:376) sc1 | [376:380) sc2 | [380:382) sc2b
__constant__ __align__(16) float c_pack[384];
#define CP_SW1A  (c_pack + 0)
#define CP_SW2   (c_pack + 32)
#define CP_SW2B  (c_pack + 288)
#define CP_WE    (c_pack + 304)
#define CP_WEB   (c_pack + 368)
#define CP_SC1   (c_pack + 372)
#define CP_SC2   (c_pack + 376)
#define CP_SC2B  (c_pack + 380)

// ---------------- f32x2 helpers ------------------------------------------------
__device__ __forceinline__ ull pack2(float x, float y){
    ull r; asm("mov.b64 %0, {%1,%2};" : "=l"(r) : "f"(x), "f"(y)); return r;
}
__device__ __forceinline__ ull fma2(ull a, ull b, ull c){
    ull d; asm("fma.rn.f32x2 %0, %1, %2, %3;" : "=l"(d) : "l"(a), "l"(b), "l"(c));
    return d;
}
__device__ __forceinline__ float2 unpack2(ull v){
    float x, y; asm("mov.b64 {%0,%1}, %2;" : "=f"(x), "=f"(y) : "l"(v));
    return make_float2(x, y);
}
__device__ __forceinline__ ull dtou(double d){ return __double_as_longlong(d); }

union F4 { float4 v; ull u[2]; float f[4]; uint32_t w[4]; };

__device__ __forceinline__ float siluf(float x){
    float t, hx = 0.5f * x;
    asm("tanh.approx.f32 %0, %1;" : "=f"(t) : "f"(hx));
    return fmaf(hx, t, hx);
}

// ---------------- warp-MMA helpers (baseline PTX, compute_103-safe) ------------
__device__ __forceinline__ uint32_t smem_u32(const void* p){
    uint32_t a;
    asm("{ .reg .u64 t; cvta.to.shared.u64 t, %1; cvt.u32.u64 %0, t; }"
        : "=r"(a) : "l"(p));
    return a;
}
__device__ __forceinline__ uint32_t swz(uint32_t x){ return x ^ ((x >> 3) & 0x70); }

#define LDSM4(r, addr) \
    asm volatile("ldmatrix.sync.aligned.m8n8.x4.shared.b16 {%0,%1,%2,%3}, [%4];" \
        : "=r"((r)[0]), "=r"((r)[1]), "=r"((r)[2]), "=r"((r)[3]) : "r"(addr))

#define LDSM4T(r, addr) \
    asm volatile("ldmatrix.sync.aligned.m8n8.x4.trans.shared.b16 {%0,%1,%2,%3}, [%4];" \
        : "=r"((r)[0]), "=r"((r)[1]), "=r"((r)[2]), "=r"((r)[3]) : "r"(addr))

#define MMA_BF16(c, a, b0, b1) \
    asm volatile("mma.sync.aligned.m16n8k16.row.col.f32.bf16.bf16.f32 " \
        "{%0,%1,%2,%3}, {%4,%5,%6,%7}, {%8,%9}, {%0,%1,%2,%3};" \
        : "+f"((c)[0]), "+f"((c)[1]), "+f"((c)[2]), "+f"((c)[3]) \
        : "r"((a)[0]), "r"((a)[1]), "r"((a)[2]), "r"((a)[3]), "r"(b0), "r"(b1))

__device__ __forceinline__ void cvt_hilo(float x, float y, uint32_t& hi, uint32_t& lo){
    asm("cvt.rn.bf16x2.f32 %0, %1, %2;" : "=r"(hi) : "f"(y), "f"(x));
    float fx = __uint_as_float(hi << 16), fy = __uint_as_float(hi & 0xffff0000u);
    asm("cvt.rn.bf16x2.f32 %0, %1, %2;" : "=r"(lo) : "f"(y - fy), "f"(x - fx));
}

// SMEM layout (dynamic)
#define OFF_EPI 0
#define OFF_AHI 2560
#define OFF_ALO (OFF_AHI + 16384)
#define OFF_BHI (OFF_ALO + 16384)
#define OFF_BLO (OFF_BHI + 8192)
#define MMA_SMEM (OFF_BLO + 8192)     // 51712

// ---------------- mma_gemm (R11 measured-best, FROZEN) -------------------------
template<int MODE>
__global__ void __launch_bounds__(256) mma_gemm(
        const float* __restrict__ Aall, const float* __restrict__ Ball,
        const float* __restrict__ biasv, float* __restrict__ Call){
    extern __shared__ char smem[];
    uint32_t sb = smem_u32(smem);
    int tid = threadIdx.x, wid = tid >> 5, lane = tid & 31;
    int warpM = wid >> 1, warpN = wid & 1;
    int row0 = blockIdx.x * 128;

    const float* A; const float* Bsrc; float* C;
    int lda, ldb, ldc, n0;
    if (MODE == 0){
        A = Aall; lda = DDc; Bsrc = Ball; ldb = NV;
        C = Call; ldc = NV; n0 = blockIdx.y * 64;
    } else if (MODE == 1){
        int z = blockIdx.z, b = z >> 2, h = z & 3;
        A = Aall + (size_t)z * TTc * KKc; lda = KKc;
        Bsrc = Ball + (size_t)b * KKc * NV + h * HDD; ldb = NV;
        C = Call + (size_t)b * TTc * DDc + h * HDD; ldc = DDc; n0 = 0;
    } else {
        A = Aall; lda = DDc; Bsrc = Ball; ldb = DDc;
        C = Call; ldc = DDc; n0 = blockIdx.y * 64;
    }

    float* sEpi = (float*)(smem + OFF_EPI);
    if (MODE == 0){
        if (tid < 64) sEpi[tid] = biasv[n0 + tid];
    }
    if (MODE == 2){
        sEpi[tid]       = g_M[(tid >> 6)*DDc + n0 + (tid & 63)];
        sEpi[256 + tid] = g_M[((256 + tid) >> 6)*DDc + n0 + (tid & 63)];
        if (tid < 64) sEpi[512 + tid] = g_cbias[n0 + tid];
    }

    float acc[2][4][4];
    #pragma unroll
    for (int mi = 0; mi < 2; mi++)
        #pragma unroll
        for (int ni = 0; ni < 4; ni++)
            #pragma unroll
            for (int q = 0; q < 4; q++) acc[mi][ni][q] = 0.f;

    int lr = lane & 7, lm = (lane >> 3) & 1, lh = lane >> 4;
    int arow = warpM*32 + lm*8 + lr;
    int btrow = lane & 15;
    int btcol = (lane >> 4) * 8;

    for (int kc = 0; kc < 4; kc++){
        int k0 = kc * 64;
        #pragma unroll
        for (int i = 0; i < 8; i++){
            int idx = i * 256 + tid;
            int r = idx >> 4, c4 = (idx & 15) * 4;
            float4 v = *(const float4*)&A[(size_t)(row0 + r)*lda + k0 + c4];
            uint32_t h0, l0, h1, l1;
            cvt_hilo(v.x, v.y, h0, l0);
            cvt_hilo(v.z, v.w, h1, l1);
            uint32_t so = swz((uint32_t)(r*128 + c4*2));
            *(uint2*)(smem + OFF_AHI + so) = make_uint2(h0, h1);
            *(uint2*)(smem + OFF_ALO + so) = make_uint2(l0, l1);
        }
        #pragma unroll
        for (int i = 0; i < 4; i++){
            int idx = i * 256 + tid;
            int k = idx >> 4, n4 = (idx & 15) * 4;
            float4 v = *(const float4*)&Bsrc[(size_t)(k0 + k)*ldb + n0 + n4];
            uint32_t h0, l0, h1, l1;
            cvt_hilo(v.x, v.y, h0, l0);
            cvt_hilo(v.z, v.w, h1, l1);
            uint32_t so = swz((uint32_t)(k*128 + n4*2));
            *(uint2*)(smem + OFF_BHI + so) = make_uint2(h0, h1);
            *(uint2*)(smem + OFF_BLO + so) = make_uint2(l0, l1);
        }
        __syncthreads();

        #pragma unroll
        for (int kk = 0; kk < 4; kk++){
            int acol = (kk*16 + lh*8) * 2;
            uint32_t ah[2][4], al[2][4], bh[2][4], bl[2][4];
            #pragma unroll
            for (int mi = 0; mi < 2; mi++){
                uint32_t off = swz((uint32_t)((arow + mi*16)*128 + acol));
                LDSM4(ah[mi], sb + OFF_AHI + off);
                LDSM4(al[mi], sb + OFF_ALO + off);
            }
            #pragma unroll
            for (int p = 0; p < 2; p++){
                uint32_t off = swz((uint32_t)((kk*16 + btrow)*128 +
                                              (warpN*32 + p*16 + btcol)*2));
                LDSM4T(bh[p], sb + OFF_BHI + off);
                LDSM4T(bl[p], sb + OFF_BLO + off);
            }
            #pragma unroll
            for (int mi = 0; mi < 2; mi++)
                #pragma unroll
                for (int ni = 0; ni < 4; ni++){
                    int p = ni >> 1, o = (ni & 1) * 2;
                    MMA_BF16(acc[mi][ni], ah[mi], bh[p][o], bh[p][o+1]);
                    MMA_BF16(acc[mi][ni], ah[mi], bl[p][o], bl[p][o+1]);
                    MMA_BF16(acc[mi][ni], al[mi], bh[p][o], bh[p][o+1]);
                }
        }
        __syncthreads();
    }

    int gid = lane >> 2, tig = lane & 3;
    #pragma unroll
    for (int mi = 0; mi < 2; mi++){
        int r0g = row0 + warpM*32 + mi*16 + gid;
        int r1g = r0g + 8;
        float e0[8], e1[8];
        if (MODE == 2){
            const float* p0 = g_ein + (size_t)r0g * 8;
            const float* p1 = g_ein + (size_t)r1g * 8;
            *(float4*)&e0[0] = *(const float4*)p0;
            *(float4*)&e0[4] = *(const float4*)(p0 + 4);
            *(float4*)&e1[0] = *(const float4*)p1;
            *(float4*)&e1[4] = *(const float4*)(p1 + 4);
        }
        #pragma unroll
        for (int ni = 0; ni < 4; ni++){
            int cl = warpN*32 + ni*8 + tig*2;
            float v0 = acc[mi][ni][0], v1 = acc[mi][ni][1];
            float v2a = acc[mi][ni][2], v3 = acc[mi][ni][3];
            if (MODE == 0){
                float b0 = sEpi[cl], b1 = sEpi[cl+1];
                v0 += b0; v1 += b1; v2a += b0; v3 += b1;
            }
            if (MODE == 2){
                float b0 = sEpi[512 + cl], b1 = sEpi[512 + cl + 1];
                v0 += b0; v1 += b1; v2a += b0; v3 += b1;
                #pragma unroll
                for (int q = 0; q < 8; q++){
                    float m0 = sEpi[q*64 + cl], m1 = sEpi[q*64 + cl + 1];
                    v0  = fmaf(e0[q], m0, v0);   v1  = fmaf(e0[q], m1, v1);
                    v2a = fmaf(e1[q], m0, v2a);  v3  = fmaf(e1[q], m1, v3);
                }
            }
            *(float2*)&C[(size_t)r0g*ldc + n0 + cl] = make_float2(v0, v1);
            *(float2*)&C[(size_t)r1g*ldc + n0 + cl] = make_float2(v2a, v3);
        }
    }
}

// ---------------- K_gather: pack small weights into one buffer -----------------
__global__ void k_gather(const float* __restrict__ sw1,  const float* __restrict__ sw2,
                         const float* __restrict__ sw2b, const float* __restrict__ we,
                         const float* __restrict__ web,  const float* __restrict__ sc1,
                         const float* __restrict__ sc2,  const float* __restrict__ sc2b){
    int i = threadIdx.x;
    float v = 0.f;
    if (i < 32)        v = sw1[i];
    else if (i < 288)  v = sw2[i - 32];
    else if (i < 304)  v = sw2b[i - 288];
    else if (i < 368)  v = we[i - 304];
    else if (i < 372)  v = web[i - 368];
    else if (i < 376)  v = sc1[i - 372];
    else if (i < 380)  v = sc2[i - 376];
    else if (i < 382)  v = sc2b[i - 380];
    g_cpack[i] = v;
}

// ---------------- K_pre: merged prep (smem-staged W1 row for conv fold) -------
__global__ void k_pre(const float* __restrict__ ceW, const float* __restrict__ ceb,
                      const float* __restrict__ W3,  const float* __restrict__ b2,
                      const float* __restrict__ b3,  const float* __restrict__ W1,
                      const float* __restrict__ b1,  const float* __restrict__ wck,
                      const float* __restrict__ cck, const float* __restrict__ Wd,
                      const float* __restrict__ bd){
    int blk = blockIdx.x;
    if (blk < 9){
        int n = threadIdx.x;
        if (n >= 256) return;
        if (blk < 8){
            int h = blk >> 1, p = blk & 1;
            float s = 0.f;
            #pragma unroll 16
            for (int d = 0; d < HDD; d++)
                s = fmaf(ceW[p*HDD + d], W3[(size_t)(h*HDD + d)*DDc + n], s);
            g_M[blk*DDc + n] = s;
        } else {
            float s = b2[n] + b3[n];
            for (int h = 0; h < 4; h++)
                #pragma unroll 16
                for (int d = 0; d < HDD; d++)
                    s = fmaf(ceb[d], W3[(size_t)(h*HDD + d)*DDc + n], s);
            g_cbias[n] = s;
        }
        return;
    }
    __shared__ float sv[256];
    int d = blk - 9;
    int c = threadIdx.x;
    const float* vec = (d < DDc) ? (W1 + (size_t)d*DDc) : b1;
    if (c < 256) sv[c] = vec[c];
    __syncthreads();
    float out = 0.f;
    if (c < 256){
        out = sv[c];
    } else if (c < 304){
        int i = c - 256;
        const float* kern = (i < 24) ? wck : cck;
        int ii = (i < 24) ? i : i - 24;
        int f = ii / 3, r = ii % 3;
        float s = 0.f;
        for (int dd = 0; dd < DDc; dd++)
            s = fmaf(sv[dd], kern[(f*DDc + dd)*3 + r], s);
        out = s;
    } else if (c == 304){
        out = (d < DDc) ? Wd[d] : bd[0];
    }
    if (d < DDc) g_Wcat[(size_t)d*NV + c] = out;
    else         g_bcat[c] = out;
}

// ---------------- K_durcomb: cumsum + combine + LN + fold (FROZEN) ------------
__global__ void k_durcomb(float* __restrict__ out_d,
                          const float* __restrict__ wcb, const float* __restrict__ wg,
                          const float* __restrict__ wbe, const float* __restrict__ ccb,
                          const float* __restrict__ cg,  const float* __restrict__ cbe,
                          const float* __restrict__ sw1, const float* __restrict__ sw1b,
                          const float* __restrict__ sc1, const float* __restrict__ sc1b){
    extern __shared__ float sU[];            // [256][52]
    __shared__ float ws[8];
    int b = blockIdx.x, k = threadIdx.x;
    int warp = k >> 5, lane = k & 31;

    float dl = fmaxf(g_v2[((size_t)b*KKc + k)*NV + 304], 0.f);
    float dv = fmaxf(__expf(dl) - 1.0f, 1e-12f);
    out_d[b*KKc + k] = dv;
    float x = dv;
    #pragma unroll
    for (int o = 1; o < 32; o <<= 1){
        float y = __shfl_up_sync(0xffffffffu, x, o);
        if (lane >= o) x += y;
    }
    if (lane == 31) ws[warp] = x;
    __syncthreads();
    if (warp == 0 && lane < 8){
        float y = ws[lane];
        #pragma unroll
        for (int o = 1; o < 8; o <<= 1){
            float z = __shfl_up_sync(0xffu, y, o, 8);
            if (lane >= o) y += z;
        }
        ws[lane] = y;
    }
    __syncthreads();
    float ev = x + (warp ? ws[warp-1] : 0.f);
    float sv = ev - dv;

    {
        const float* src = g_v2 + ((size_t)b*KKc + k)*NV + 256;
        float* row = sU + k*52;
        #pragma unroll
        for (int q = 0; q < 12; q++)
            *(float4*)&row[q*4] = *(const float4*)&src[q*4];
    }
    __syncthreads();

    const float* rm = sU + (k-1)*52;
    const float* rc = sU + k*52;
    const float* rp = sU + (k+1)*52;
    float wy[8], cy[8];
    #pragma unroll
    for (int f = 0; f < 8; f++){
        wy[f] = wcb[f] + rc[f*3 + 1];
        cy[f] = ccb[f] + rc[24 + f*3 + 1];
    }
    if (k > 0){
        #pragma unroll
        for (int f = 0; f < 8; f++){
            wy[f] += rm[f*3 + 0];
            cy[f] += rm[24 + f*3 + 0];
        }
    }
    if (k < KKc-1){
        #pragma unroll
        for (int f = 0; f < 8; f++){
            wy[f] += rp[f*3 + 2];
            cy[f] += rp[24 + f*3 + 2];
        }
    }
    float muw = 0.f, muc = 0.f;
    #pragma unroll
    for (int f = 0; f < 8; f++){ muw += wy[f]; muc += cy[f]; }
    muw *= 0.125f; muc *= 0.125f;
    float vw = 0.f, vc = 0.f;
    #pragma unroll
    for (int f = 0; f < 8; f++){
        float a = wy[f]-muw; vw += a*a;
        float c = cy[f]-muc; vc += c*c;
    }
    vw *= 0.125f; vc *= 0.125f;
    float rw = rsqrtf(vw + 1e-5f), rcv = rsqrtf(vc + 1e-5f);
    float wf[8], cf[8];
    #pragma unroll
    for (int f = 0; f < 8; f++){
        wf[f] = siluf((wy[f]-muw)*rw*wg[f] + wbe[f]);
        cf[f] = siluf((cy[f]-muc)*rcv*cg[f] + cbe[f]);
    }
    float* bw = g_baseW + ((size_t)b*KKc + k)*16;
    #pragma unroll
    for (int j = 0; j < 16; j++){
        float s2 = sw1b[j];
        #pragma unroll
        for (int f = 0; f < 8; f++) s2 = fmaf(wf[f], sw1[(2+f)*16 + j], s2);
        s2 = fmaf(-sv, sw1[j], fmaf(ev, sw1[16 + j], s2));
        bw[j] = s2;
    }
    float* bc = g_baseC + ((size_t)b*KKc + k)*2;
    #pragma unroll
    for (int j = 0; j < 2; j++){
        float s2 = sc1b[j];
        #pragma unroll
        for (int f = 0; f < 8; f++) s2 = fmaf(cf[f], sc1[(2+f)*2 + j], s2);
        s2 = fmaf(-sv, sc1[j], fmaf(ev, sc1[2 + j], s2));
        bc[j] = s2;
    }
}

// ---------------- K4: warp-per-t MLP, smem-staged bases (R14 exact, occ 2) ----
__global__ void __launch_bounds__(256, 2) k_mlp(float* __restrict__ attn_out){
    __shared__ __align__(16) float sW[4*KKc*4];    // 16 KB, [q][k][4]
    __shared__ __align__(16) float sC[KKc*2];      // 2 KB,  [k][2]
    int tid = threadIdx.x, b = blockIdx.y;

    {
        const float* src = g_baseW + ((size_t)b*KKc + tid)*16;
        #pragma unroll
        for (int q = 0; q < 4; q++){
            float4 v = *(const float4*)(src + q*4);
            *(float4*)&sW[(q*KKc + tid)*4] = v;
        }
        *(float2*)&sC[tid*2] = *(const float2*)(g_baseC + ((size_t)b*KKc + tid)*2);
    }
    __syncthreads();

    int warp = tid >> 5, lane = tid & 31;
    int t = (blockIdx.x << 3) + warp;
    float ts = (float)(t + 1);
    ull ts2 = pack2(ts, ts);

    ull gw2[8];
    #pragma unroll
    for (int q = 0; q < 8; q++){
        float g0 = CP_SW1A[2*q]   - CP_SW1A[16 + 2*q];
        float g1 = CP_SW1A[2*q+1] - CP_SW1A[16 + 2*q+1];
        gw2[q] = pack2(g0, g1);
    }
    float cd0 = CP_SC1[0] - CP_SC1[2], cd1 = CP_SC1[1] - CP_SC1[3];

    const double* w2d = (const double*)CP_SW2;
    const double* b2d = (const double*)CP_SW2B;
    const double* wed  = (const double*)CP_WE;
    const double* webd = (const double*)CP_WEB;

    float lg[8][4];
    float hcv0[8], hcv1[8];

    #pragma unroll
    for (int j = 0; j < 8; j++){
        int kk = lane + 32*j;                  // strided ownership
        F4 w0 = *(const F4*)&sW[(0*KKc + kk)*4];
        F4 w1 = *(const F4*)&sW[(1*KKc + kk)*4];
        F4 w2 = *(const F4*)&sW[(2*KKc + kk)*4];
        F4 w3 = *(const F4*)&sW[(3*KKc + kk)*4];
        ull bw[8] = {w0.u[0], w0.u[1], w1.u[0], w1.u[1],
                     w2.u[0], w2.u[1], w3.u[0], w3.u[1]};
        float h1[16];
        #pragma unroll
        for (int q = 0; q < 8; q++){
            ull tv = fma2(ts2, gw2[q], bw[q]);
            float2 f = unpack2(tv);
            h1[2*q]   = siluf(f.x);
            h1[2*q+1] = siluf(f.y);
        }
        ull acc2[8];
        #pragma unroll
        for (int q = 0; q < 8; q++) acc2[q] = dtou(b2d[q]);
        #pragma unroll
        for (int j1 = 0; j1 < 16; j1++){
            ull a2 = pack2(h1[j1], h1[j1]);
            #pragma unroll
            for (int q = 0; q < 8; q++)
                acc2[q] = fma2(a2, dtou(w2d[j1*8 + q]), acc2[q]);
        }
        ull lg2[2] = {dtou(webd[0]), dtou(webd[1])};
        #pragma unroll
        for (int j2 = 0; j2 < 8; j2++){
            float2 f = unpack2(acc2[j2]);
            float ha = siluf(f.x), hb = siluf(f.y);
            int jj = 2*j2;
            ull ha2 = pack2(ha, ha), hb2 = pack2(hb, hb);
            lg2[0] = fma2(ha2, dtou(wed[jj*2+0]), lg2[0]);
            lg2[1] = fma2(ha2, dtou(wed[jj*2+1]), lg2[1]);
            lg2[0] = fma2(hb2, dtou(wed[(jj+1)*2+0]), lg2[0]);
            lg2[1] = fma2(hb2, dtou(wed[(jj+1)*2+1]), lg2[1]);
        }
        { float2 f = unpack2(lg2[0]); lg[j][0] = f.x; lg[j][1] = f.y; }
        { float2 f = unpack2(lg2[1]); lg[j][2] = f.x; lg[j][3] = f.y; }

        float2 bc2 = *(const float2*)&sC[kk*2];
        float c10 = siluf(fmaf(ts, cd0, bc2.x));
        float c11 = siluf(fmaf(ts, cd1, bc2.y));
        hcv0[j] = siluf(fmaf(c10, CP_SC2[0], fmaf(c11, CP_SC2[2], CP_SC2B[0])));
        hcv1[j] = siluf(fmaf(c10, CP_SC2[1], fmaf(c11, CP_SC2[3], CP_SC2B[1])));
    }

    float gm[4];
    #pragma unroll
    for (int h = 0; h < 4; h++){
        float m = lg[0][h];
        #pragma unroll
        for (int j = 1; j < 8; j++) m = fmaxf(m, lg[j][h]);
        #pragma unroll
        for (int o = 16; o > 0; o >>= 1)
            m = fmaxf(m, __shfl_xor_sync(0xffffffffu, m, o));
        gm[h] = m;
    }
    float inv[4];
    #pragma unroll
    for (int h = 0; h < 4; h++){
        float s = 0.f;
        #pragma unroll
        for (int j = 0; j < 8; j++){
            lg[j][h] = __expf(lg[j][h] - gm[h]);
            s += lg[j][h];
        }
        #pragma unroll
        for (int o = 16; o > 0; o >>= 1)
            s += __shfl_xor_sync(0xffffffffu, s, o);
        inv[h] = __fdividef(1.f, s);
    }

    float e8[8];
    #pragma unroll
    for (int i = 0; i < 8; i++) e8[i] = 0.f;
    #pragma unroll
    for (int h = 0; h < 4; h++){
        float* dst = attn_out + ((size_t)(b*4 + h)*TTc + t)*KKc + lane;
        #pragma unroll
        for (int j = 0; j < 8; j++){
            float a = lg[j][h] * inv[h];
            e8[h*2]   = fmaf(a, hcv0[j], e8[h*2]);
            e8[h*2+1] = fmaf(a, hcv1[j], e8[h*2+1]);
            dst[32*j] = a;
        }
    }
    #pragma unroll
    for (int i = 0; i < 8; i++){
        #pragma unroll
        for (int o = 16; o > 0; o >>= 1)
            e8[i] += __shfl_xor_sync(0xffffffffu, e8[i], o);
    }
    if (lane == 0){
        float* dst = g_ein + ((size_t)b*TTc + t)*8;
        *(float4*)dst       = *(float4*)&e8[0];
        *(float4*)(dst + 4) = *(float4*)&e8[4];
    }
}

// ---------------- launch ------------------------------------------------------
extern "C" void kernel_launch(void* const* d_in, const int* in_sizes, int n_in,
                              void* d_out, int out_size){
    const float* phs  = (const float*)d_in[0];
    const float* Wd   = (const float*)d_in[4];
    const float* bd   = (const float*)d_in[5];
    const float* W1   = (const float*)d_in[6];
    const float* b1   = (const float*)d_in[7];
    const float* W2   = (const float*)d_in[8];
    const float* b2   = (const float*)d_in[9];
    const float* W3   = (const float*)d_in[10];
    const float* b3   = (const float*)d_in[11];
    const float* wck  = (const float*)d_in[12];
    const float* wcb  = (const float*)d_in[13];
    const float* wlg  = (const float*)d_in[14];
    const float* wlb  = (const float*)d_in[15];
    const float* cck  = (const float*)d_in[16];
    const float* ccb  = (const float*)d_in[17];
    const float* clg  = (const float*)d_in[18];
    const float* clb  = (const float*)d_in[19];
    const float* sw1  = (const float*)d_in[20];
    const float* sw1b = (const float*)d_in[21];
    const float* sw2  = (const float*)d_in[22];
    const float* sw2b = (const float*)d_in[23];
    const float* sc1  = (const float*)d_in[24];
    const float* sc1b = (const float*)d_in[25];
    const float* sc2  = (const float*)d_in[26];
    const float* sc2b = (const float*)d_in[27];
    const float* weW  = (const float*)d_in[28];
    const float* web  = (const float*)d_in[29];
    const float* ceW  = (const float*)d_in[30];
    const float* ceb  = (const float*)d_in[31];
    (void)in_sizes; (void)n_in;

    float* outp = (float*)d_out;
    const size_t nOut  = (size_t)BB*TTc*DDc;
    const size_t nD    = (size_t)BB*KKc;
    const size_t nAttn = (size_t)BB*NHH*TTc*KKc;
    bool full = ((size_t)out_size >= nOut + nD + nAttn);

    float *vP, *oLP, *attnP, *dP, *bcatP, *WcatP, *cpackP;
    cudaGetSymbolAddress((void**)&vP,     g_v2);
    cudaGetSymbolAddress((void**)&oLP,    g_oL);
    cudaGetSymbolAddress((void**)&bcatP,  g_bcat);
    cudaGetSymbolAddress((void**)&WcatP,  g_Wcat);
    cudaGetSymbolAddress((void**)&cpackP, g_cpack);
    if (full){
        dP    = outp + nOut;
        attnP = outp + nOut + nD;
    } else {
        cudaGetSymbolAddress((void**)&dP,    g_dF);
        cudaGetSymbolAddress((void**)&attnP, g_attnF);
    }

    cudaFuncSetAttribute(mma_gemm<0>, cudaFuncAttributeMaxDynamicSharedMemorySize, MMA_SMEM);
    cudaFuncSetAttribute(mma_gemm<1>, cudaFuncAttributeMaxDynamicSharedMemorySize, MMA_SMEM);
    cudaFuncSetAttribute(mma_gemm<2>, cudaFuncAttributeMaxDynamicSharedMemorySize, MMA_SMEM);
    cudaFuncSetAttribute(k_durcomb, cudaFuncAttributeMaxDynamicSharedMemorySize,
                         KKc*52*(int)sizeof(float));

    // gather small weights into one buffer, then ONE constant-bank upload
    k_gather<<<1, 384>>>(sw1, sw2, sw2b, weW, web, sc1, sc2, sc2b);
    cudaMemcpyToSymbolAsync(c_pack, cpackP, 384*sizeof(float), 0,
                            cudaMemcpyDeviceToDevice);

    k_pre<<<266, NV>>>(ceW, ceb, W3, b2, b3, W1, b1, wck, cck, Wd, bd);
    mma_gemm<0><<<dim3(BB*KKc/128, NV/64), 256, MMA_SMEM>>>(phs, WcatP, bcatP, vP);
    k_durcomb<<<BB, KKc, KKc*52*sizeof(float)>>>(dP, wcb, wlg, wlb, ccb, clg, clb,
                                                 sw1, sw1b, sc1, sc1b);
    k_mlp<<<dim3(TTc/8, BB), 256>>>(attnP);
    mma_gemm<1><<<dim3(TTc/128, 1, BB*NHH), 256, MMA_SMEM>>>(attnP, vP, nullptr, oLP);
    mma_gemm<2><<<dim3(BB*TTc/128, DDc/64), 256, MMA_SMEM>>>(oLP, W2, nullptr, outp);
}

// round 17
// speedup vs baseline: 1.0896x; 1.0307x over previous
#include <cuda_runtime.h>
#include <cuda_bf16.h>
#include <cstdint>

#define BB   8
#define KKc  256
#define DDc  256
#define TTc  2048
#define NHH  4
#define HDD  64
#define NV   320        // extended v width: 256 v | 48 conv | 1 dur | 15 pad

typedef unsigned long long ull;

// ---------------- scratch (__device__ globals) --------------------------------
__device__ __align__(16) float g_v2[(size_t)BB*KKc*NV];
__device__ __align__(16) float g_Wcat[DDc*NV];
__device__ __align__(16) float g_bcat[NV];
__device__ __align__(16) float g_s[BB*KKc];
__device__ __align__(16) float g_e[BB*KKc];
__device__ __align__(16) float g_baseW[BB*KKc*16];   // row layout [b][k][16]
__device__ __align__(16) float g_baseC[BB*KKc*2];
__device__ __align__(16) float g_ein[(size_t)BB*TTc*8];
__device__ __align__(16) float g_oL[(size_t)BB*TTc*DDc];
__device__ __align__(16) float g_M[8*DDc];
__device__ __align__(16) float g_cbias[DDc];
__device__ __align__(16) float g_cpack[384];
__device__ __align__(16) float g_dF[BB*KKc];
__device__ __align__(16) float g_attnF[(size_t)BB*NHH*TTc*KKc];

// ---------------- packed constant bank (single memcpy) -------------------------
__constant__ __align__(16) float c_pack[384];
#define CP_SW1A  (c_pack + 0)
#define CP_SW2   (c_pack + 32)
#define CP_SW2B  (c_pack + 288)
#define CP_WE    (c_pack + 304)
#define CP_WEB   (c_pack + 368)
#define CP_SC1   (c_pack + 372)
#define CP_SC2   (c_pack + 376)
#define CP_SC2B  (c_pack + 380)

// ---------------- f32x2 helpers ------------------------------------------------
__device__ __forceinline__ ull pack2(float x, float y){
    ull r; asm("mov.b64 %0, {%1,%2};" : "=l"(r) : "f"(x), "f"(y)); return r;
}
__device__ __forceinline__ ull fma2(ull a, ull b, ull c){
    ull d; asm("fma.rn.f32x2 %0, %1, %2, %3;" : "=l"(d) : "l"(a), "l"(b), "l"(c));
    return d;
}
__device__ __forceinline__ float2 unpack2(ull v){
    float x, y; asm("mov.b64 {%0,%1}, %2;" : "=f"(x), "=f"(y) : "l"(v));
    return make_float2(x, y);
}
__device__ __forceinline__ ull dtou(double d){ return __double_as_longlong(d); }

union F4 { float4 v; ull u[2]; float f[4]; uint32_t w[4]; };

__device__ __forceinline__ float siluf(float x){
    float t, hx = 0.5f * x;
    asm("tanh.approx.f32 %0, %1;" : "=f"(t) : "f"(hx));
    return fmaf(hx, t, hx);
}

// ---------------- warp-MMA helpers (baseline PTX, compute_103-safe) ------------
__device__ __forceinline__ uint32_t smem_u32(const void* p){
    uint32_t a;
    asm("{ .reg .u64 t; cvta.to.shared.u64 t, %1; cvt.u32.u64 %0, t; }"
        : "=r"(a) : "l"(p));
    return a;
}
__device__ __forceinline__ uint32_t swz(uint32_t x){ return x ^ ((x >> 3) & 0x70); }

#define LDSM4(r, addr) \
    asm volatile("ldmatrix.sync.aligned.m8n8.x4.shared.b16 {%0,%1,%2,%3}, [%4];" \
        : "=r"((r)[0]), "=r"((r)[1]), "=r"((r)[2]), "=r"((r)[3]) : "r"(addr))

#define LDSM4T(r, addr) \
    asm volatile("ldmatrix.sync.aligned.m8n8.x4.trans.shared.b16 {%0,%1,%2,%3}, [%4];" \
        : "=r"((r)[0]), "=r"((r)[1]), "=r"((r)[2]), "=r"((r)[3]) : "r"(addr))

#define MMA_BF16(c, a, b0, b1) \
    asm volatile("mma.sync.aligned.m16n8k16.row.col.f32.bf16.bf16.f32 " \
        "{%0,%1,%2,%3}, {%4,%5,%6,%7}, {%8,%9}, {%0,%1,%2,%3};" \
        : "+f"((c)[0]), "+f"((c)[1]), "+f"((c)[2]), "+f"((c)[3]) \
        : "r"((a)[0]), "r"((a)[1]), "r"((a)[2]), "r"((a)[3]), "r"(b0), "r"(b1))

__device__ __forceinline__ void cvt_hilo(float x, float y, uint32_t& hi, uint32_t& lo){
    asm("cvt.rn.bf16x2.f32 %0, %1, %2;" : "=r"(hi) : "f"(y), "f"(x));
    float fx = __uint_as_float(hi << 16), fy = __uint_as_float(hi & 0xffff0000u);
    asm("cvt.rn.bf16x2.f32 %0, %1, %2;" : "=r"(lo) : "f"(y - fy), "f"(x - fx));
}

// SMEM layout (dynamic)
#define OFF_EPI 0
#define OFF_AHI 2560
#define OFF_ALO (OFF_AHI + 16384)
#define OFF_BHI (OFF_ALO + 16384)
#define OFF_BLO (OFF_BHI + 8192)
#define MMA_SMEM (OFF_BLO + 8192)     // 51712

// ---------------- mma_gemm (R11 measured-best, FROZEN) -------------------------
template<int MODE>
__global__ void __launch_bounds__(256) mma_gemm(
        const float* __restrict__ Aall, const float* __restrict__ Ball,
        const float* __restrict__ biasv, float* __restrict__ Call){
    extern __shared__ char smem[];
    uint32_t sb = smem_u32(smem);
    int tid = threadIdx.x, wid = tid >> 5, lane = tid & 31;
    int warpM = wid >> 1, warpN = wid & 1;
    int row0 = blockIdx.x * 128;

    const float* A; const float* Bsrc; float* C;
    int lda, ldb, ldc, n0;
    if (MODE == 0){
        A = Aall; lda = DDc; Bsrc = Ball; ldb = NV;
        C = Call; ldc = NV; n0 = blockIdx.y * 64;
    } else if (MODE == 1){
        int z = blockIdx.z, b = z >> 2, h = z & 3;
        A = Aall + (size_t)z * TTc * KKc; lda = KKc;
        Bsrc = Ball + (size_t)b * KKc * NV + h * HDD; ldb = NV;
        C = Call + (size_t)b * TTc * DDc + h * HDD; ldc = DDc; n0 = 0;
    } else {
        A = Aall; lda = DDc; Bsrc = Ball; ldb = DDc;
        C = Call; ldc = DDc; n0 = blockIdx.y * 64;
    }

    float* sEpi = (float*)(smem + OFF_EPI);
    if (MODE == 0){
        if (tid < 64) sEpi[tid] = biasv[n0 + tid];
    }
    if (MODE == 2){
        sEpi[tid]       = g_M[(tid >> 6)*DDc + n0 + (tid & 63)];
        sEpi[256 + tid] = g_M[((256 + tid) >> 6)*DDc + n0 + (tid & 63)];
        if (tid < 64) sEpi[512 + tid] = g_cbias[n0 + tid];
    }

    float acc[2][4][4];
    #pragma unroll
    for (int mi = 0; mi < 2; mi++)
        #pragma unroll
        for (int ni = 0; ni < 4; ni++)
            #pragma unroll
            for (int q = 0; q < 4; q++) acc[mi][ni][q] = 0.f;

    int lr = lane & 7, lm = (lane >> 3) & 1, lh = lane >> 4;
    int arow = warpM*32 + lm*8 + lr;
    int btrow = lane & 15;
    int btcol = (lane >> 4) * 8;

    for (int kc = 0; kc < 4; kc++){
        int k0 = kc * 64;
        #pragma unroll
        for (int i = 0; i < 8; i++){
            int idx = i * 256 + tid;
            int r = idx >> 4, c4 = (idx & 15) * 4;
            float4 v = *(const float4*)&A[(size_t)(row0 + r)*lda + k0 + c4];
            uint32_t h0, l0, h1, l1;
            cvt_hilo(v.x, v.y, h0, l0);
            cvt_hilo(v.z, v.w, h1, l1);
            uint32_t so = swz((uint32_t)(r*128 + c4*2));
            *(uint2*)(smem + OFF_AHI + so) = make_uint2(h0, h1);
            *(uint2*)(smem + OFF_ALO + so) = make_uint2(l0, l1);
        }
        #pragma unroll
        for (int i = 0; i < 4; i++){
            int idx = i * 256 + tid;
            int k = idx >> 4, n4 = (idx & 15) * 4;
            float4 v = *(const float4*)&Bsrc[(size_t)(k0 + k)*ldb + n0 + n4];
            uint32_t h0, l0, h1, l1;
            cvt_hilo(v.x, v.y, h0, l0);
            cvt_hilo(v.z, v.w, h1, l1);
            uint32_t so = swz((uint32_t)(k*128 + n4*2));
            *(uint2*)(smem + OFF_BHI + so) = make_uint2(h0, h1);
            *(uint2*)(smem + OFF_BLO + so) = make_uint2(l0, l1);
        }
        __syncthreads();

        #pragma unroll
        for (int kk = 0; kk < 4; kk++){
            int acol = (kk*16 + lh*8) * 2;
            uint32_t ah[2][4], al[2][4], bh[2][4], bl[2][4];
            #pragma unroll
            for (int mi = 0; mi < 2; mi++){
                uint32_t off = swz((uint32_t)((arow + mi*16)*128 + acol));
                LDSM4(ah[mi], sb + OFF_AHI + off);
                LDSM4(al[mi], sb + OFF_ALO + off);
            }
            #pragma unroll
            for (int p = 0; p < 2; p++){
                uint32_t off = swz((uint32_t)((kk*16 + btrow)*128 +
                                              (warpN*32 + p*16 + btcol)*2));
                LDSM4T(bh[p], sb + OFF_BHI + off);
                LDSM4T(bl[p], sb + OFF_BLO + off);
            }
            #pragma unroll
            for (int mi = 0; mi < 2; mi++)
                #pragma unroll
                for (int ni = 0; ni < 4; ni++){
                    int p = ni >> 1, o = (ni & 1) * 2;
                    MMA_BF16(acc[mi][ni], ah[mi], bh[p][o], bh[p][o+1]);
                    MMA_BF16(acc[mi][ni], ah[mi], bl[p][o], bl[p][o+1]);
                    MMA_BF16(acc[mi][ni], al[mi], bh[p][o], bh[p][o+1]);
                }
        }
        __syncthreads();
    }

    int gid = lane >> 2, tig = lane & 3;
    #pragma unroll
    for (int mi = 0; mi < 2; mi++){
        int r0g = row0 + warpM*32 + mi*16 + gid;
        int r1g = r0g + 8;
        float e0[8], e1[8];
        if (MODE == 2){
            const float* p0 = g_ein + (size_t)r0g * 8;
            const float* p1 = g_ein + (size_t)r1g * 8;
            *(float4*)&e0[0] = *(const float4*)p0;
            *(float4*)&e0[4] = *(const float4*)(p0 + 4);
            *(float4*)&e1[0] = *(const float4*)p1;
            *(float4*)&e1[4] = *(const float4*)(p1 + 4);
        }
        #pragma unroll
        for (int ni = 0; ni < 4; ni++){
            int cl = warpN*32 + ni*8 + tig*2;
            float v0 = acc[mi][ni][0], v1 = acc[mi][ni][1];
            float v2a = acc[mi][ni][2], v3 = acc[mi][ni][3];
            if (MODE == 0){
                float b0 = sEpi[cl], b1 = sEpi[cl+1];
                v0 += b0; v1 += b1; v2a += b0; v3 += b1;
            }
            if (MODE == 2){
                float b0 = sEpi[512 + cl], b1 = sEpi[512 + cl + 1];
                v0 += b0; v1 += b1; v2a += b0; v3 += b1;
                #pragma unroll
                for (int q = 0; q < 8; q++){
                    float m0 = sEpi[q*64 + cl], m1 = sEpi[q*64 + cl + 1];
                    v0  = fmaf(e0[q], m0, v0);   v1  = fmaf(e0[q], m1, v1);
                    v2a = fmaf(e1[q], m0, v2a);  v3  = fmaf(e1[q], m1, v3);
                }
            }
            *(float2*)&C[(size_t)r0g*ldc + n0 + cl] = make_float2(v0, v1);
            *(float2*)&C[(size_t)r1g*ldc + n0 + cl] = make_float2(v2a, v3);
        }
    }
}

// ---------------- K_pre: merged prep + gather (blk 266) ------------------------
__global__ void k_pre(const float* __restrict__ ceW, const float* __restrict__ ceb,
                      const float* __restrict__ W3,  const float* __restrict__ b2,
                      const float* __restrict__ b3,  const float* __restrict__ W1,
                      const float* __restrict__ b1,  const float* __restrict__ wck,
                      const float* __restrict__ cck, const float* __restrict__ Wd,
                      const float* __restrict__ bd,
                      const float* __restrict__ sw1,  const float* __restrict__ sw2,
                      const float* __restrict__ sw2b, const float* __restrict__ we,
                      const float* __restrict__ web,  const float* __restrict__ sc1,
                      const float* __restrict__ sc2,  const float* __restrict__ sc2b){
    int blk = blockIdx.x;
    if (blk == 266){
        // gather small weights into g_cpack (384 entries, 320 threads)
        for (int i = threadIdx.x; i < 384; i += NV){
            float v = 0.f;
            if (i < 32)        v = sw1[i];
            else if (i < 288)  v = sw2[i - 32];
            else if (i < 304)  v = sw2b[i - 288];
            else if (i < 368)  v = we[i - 304];
            else if (i < 372)  v = web[i - 368];
            else if (i < 376)  v = sc1[i - 372];
            else if (i < 380)  v = sc2[i - 376];
            else if (i < 382)  v = sc2b[i - 380];
            g_cpack[i] = v;
        }
        return;
    }
    if (blk < 9){
        int n = threadIdx.x;
        if (n >= 256) return;
        if (blk < 8){
            int h = blk >> 1, p = blk & 1;
            float s = 0.f;
            #pragma unroll 16
            for (int d = 0; d < HDD; d++)
                s = fmaf(ceW[p*HDD + d], W3[(size_t)(h*HDD + d)*DDc + n], s);
            g_M[blk*DDc + n] = s;
        } else {
            float s = b2[n] + b3[n];
            for (int h = 0; h < 4; h++)
                #pragma unroll 16
                for (int d = 0; d < HDD; d++)
                    s = fmaf(ceb[d], W3[(size_t)(h*HDD + d)*DDc + n], s);
            g_cbias[n] = s;
        }
        return;
    }
    __shared__ float sv[256];
    int d = blk - 9;
    int c = threadIdx.x;
    const float* vec = (d < DDc) ? (W1 + (size_t)d*DDc) : b1;
    if (c < 256) sv[c] = vec[c];
    __syncthreads();
    float out = 0.f;
    if (c < 256){
        out = sv[c];
    } else if (c < 304){
        int i = c - 256;
        const float* kern = (i < 24) ? wck : cck;
        int ii = (i < 24) ? i : i - 24;
        int f = ii / 3, r = ii % 3;
        // 4 independent partial chains to break FMA latency serialization
        float s0 = 0.f, s1 = 0.f, s2 = 0.f, s3 = 0.f;
        for (int dd = 0; dd < DDc; dd += 4){
            s0 = fmaf(sv[dd+0], kern[(f*DDc + dd+0)*3 + r], s0);
            s1 = fmaf(sv[dd+1], kern[(f*DDc + dd+1)*3 + r], s1);
            s2 = fmaf(sv[dd+2], kern[(f*DDc + dd+2)*3 + r], s2);
            s3 = fmaf(sv[dd+3], kern[(f*DDc + dd+3)*3 + r], s3);
        }
        out = (s0 + s1) + (s2 + s3);
    } else if (c == 304){
        out = (d < DDc) ? Wd[d] : bd[0];
    }
    if (d < DDc) g_Wcat[(size_t)d*NV + c] = out;
    else         g_bcat[c] = out;
}

// ---------------- K_scan: duration + cumsum only ------------------------------
__global__ void k_scan(float* __restrict__ out_d){
    __shared__ float ws[8];
    int b = blockIdx.x, k = threadIdx.x;
    int warp = k >> 5, lane = k & 31;
    float dl = fmaxf(g_v2[((size_t)b*KKc + k)*NV + 304], 0.f);
    float dv = fmaxf(__expf(dl) - 1.0f, 1e-12f);
    out_d[b*KKc + k] = dv;
    float x = dv;
    #pragma unroll
    for (int o = 1; o < 32; o <<= 1){
        float y = __shfl_up_sync(0xffffffffu, x, o);
        if (lane >= o) x += y;
    }
    if (lane == 31) ws[warp] = x;
    __syncthreads();
    if (warp == 0 && lane < 8){
        float y = ws[lane];
        #pragma unroll
        for (int o = 1; o < 8; o <<= 1){
            float z = __shfl_up_sync(0xffu, y, o, 8);
            if (lane >= o) y += z;
        }
        ws[lane] = y;
    }
    __syncthreads();
    float e = x + (warp ? ws[warp-1] : 0.f);
    g_e[b*KKc + k] = e;
    g_s[b*KKc + k] = e - dv;
}

// ---------------- K_comb: 3-tap combine + LN + SiLU + fold (16 blocks) --------
__global__ void k_comb(const float* __restrict__ wcb, const float* __restrict__ wg,
                       const float* __restrict__ wbe, const float* __restrict__ ccb,
                       const float* __restrict__ cg,  const float* __restrict__ cbe,
                       const float* __restrict__ sw1, const float* __restrict__ sw1b,
                       const float* __restrict__ sc1, const float* __restrict__ sc1b){
    int half = blockIdx.x & 1, b = blockIdx.x >> 1;
    int k = threadIdx.x;
    int kg = half*128 + k;
    __shared__ float sU[130][52];        // rows [base-1 .. base+128], 27 KB
    for (int i = threadIdx.x; i < 130; i += 128){
        int row = half*128 + i - 1;
        if (row >= 0 && row < KKc){
            const float* src = g_v2 + ((size_t)b*KKc + row)*NV + 256;
            #pragma unroll
            for (int q = 0; q < 12; q++)
                *(float4*)&sU[i][q*4] = *(const float4*)&src[q*4];
        } else {
            #pragma unroll
            for (int q = 0; q < 12; q++)
                *(float4*)&sU[i][q*4] = make_float4(0.f,0.f,0.f,0.f);
        }
    }
    __syncthreads();

    float wy[8], cy[8];
    #pragma unroll
    for (int f = 0; f < 8; f++){
        wy[f] = wcb[f] + sU[k+1][f*3 + 1]      + sU[k][f*3 + 0]      + sU[k+2][f*3 + 2];
        cy[f] = ccb[f] + sU[k+1][24 + f*3 + 1] + sU[k][24 + f*3 + 0] + sU[k+2][24 + f*3 + 2];
    }
    float muw = 0.f, muc = 0.f;
    #pragma unroll
    for (int f = 0; f < 8; f++){ muw += wy[f]; muc += cy[f]; }
    muw *= 0.125f; muc *= 0.125f;
    float vw = 0.f, vc = 0.f;
    #pragma unroll
    for (int f = 0; f < 8; f++){
        float a = wy[f]-muw; vw += a*a;
        float c = cy[f]-muc; vc += c*c;
    }
    vw *= 0.125f; vc *= 0.125f;
    float rw = rsqrtf(vw + 1e-5f), rcv = rsqrtf(vc + 1e-5f);
    float wf[8], cf[8];
    #pragma unroll
    for (int f = 0; f < 8; f++){
        wf[f] = siluf((wy[f]-muw)*rw*wg[f] + wbe[f]);
        cf[f] = siluf((cy[f]-muc)*rcv*cg[f] + cbe[f]);
    }
    float sv = g_s[b*KKc + kg], ev = g_e[b*KKc + kg];
    float* bw = g_baseW + ((size_t)b*KKc + kg)*16;
    #pragma unroll
    for (int j = 0; j < 16; j++){
        float s2 = sw1b[j];
        #pragma unroll
        for (int f = 0; f < 8; f++) s2 = fmaf(wf[f], sw1[(2+f)*16 + j], s2);
        s2 = fmaf(-sv, sw1[j], fmaf(ev, sw1[16 + j], s2));
        bw[j] = s2;
    }
    float* bc = g_baseC + ((size_t)b*KKc + kg)*2;
    #pragma unroll
    for (int j = 0; j < 2; j++){
        float s2 = sc1b[j];
        #pragma unroll
        for (int f = 0; f < 8; f++) s2 = fmaf(cf[f], sc1[(2+f)*2 + j], s2);
        s2 = fmaf(-sv, sc1[j], fmaf(ev, sc1[2 + j], s2));
        bc[j] = s2;
    }
}

// ---------------- K4: warp-per-t MLP, smem-staged bases (FROZEN) --------------
__global__ void __launch_bounds__(256, 2) k_mlp(float* __restrict__ attn_out){
    __shared__ __align__(16) float sW[4*KKc*4];    // 16 KB, [q][k][4]
    __shared__ __align__(16) float sC[KKc*2];      // 2 KB,  [k][2]
    int tid = threadIdx.x, b = blockIdx.y;

    {
        const float* src = g_baseW + ((size_t)b*KKc + tid)*16;
        #pragma unroll
        for (int q = 0; q < 4; q++){
            float4 v = *(const float4*)(src + q*4);
            *(float4*)&sW[(q*KKc + tid)*4] = v;
        }
        *(float2*)&sC[tid*2] = *(const float2*)(g_baseC + ((size_t)b*KKc + tid)*2);
    }
    __syncthreads();

    int warp = tid >> 5, lane = tid & 31;
    int t = (blockIdx.x << 3) + warp;
    float ts = (float)(t + 1);
    ull ts2 = pack2(ts, ts);

    ull gw2[8];
    #pragma unroll
    for (int q = 0; q < 8; q++){
        float g0 = CP_SW1A[2*q]   - CP_SW1A[16 + 2*q];
        float g1 = CP_SW1A[2*q+1] - CP_SW1A[16 + 2*q+1];
        gw2[q] = pack2(g0, g1);
    }
    float cd0 = CP_SC1[0] - CP_SC1[2], cd1 = CP_SC1[1] - CP_SC1[3];

    const double* w2d = (const double*)CP_SW2;
    const double* b2d = (const double*)CP_SW2B;
    const double* wed  = (const double*)CP_WE;
    const double* webd = (const double*)CP_WEB;

    float lg[8][4];
    float hcv0[8], hcv1[8];

    #pragma unroll
    for (int j = 0; j < 8; j++){
        int kk = lane + 32*j;                  // strided ownership
        F4 w0 = *(const F4*)&sW[(0*KKc + kk)*4];
        F4 w1 = *(const F4*)&sW[(1*KKc + kk)*4];
        F4 w2 = *(const F4*)&sW[(2*KKc + kk)*4];
        F4 w3 = *(const F4*)&sW[(3*KKc + kk)*4];
        ull bw[8] = {w0.u[0], w0.u[1], w1.u[0], w1.u[1],
                     w2.u[0], w2.u[1], w3.u[0], w3.u[1]};
        float h1[16];
        #pragma unroll
        for (int q = 0; q < 8; q++){
            ull tv = fma2(ts2, gw2[q], bw[q]);
            float2 f = unpack2(tv);
            h1[2*q]   = siluf(f.x);
            h1[2*q+1] = siluf(f.y);
        }
        ull acc2[8];
        #pragma unroll
        for (int q = 0; q < 8; q++) acc2[q] = dtou(b2d[q]);
        #pragma unroll
        for (int j1 = 0; j1 < 16; j1++){
            ull a2 = pack2(h1[j1], h1[j1]);
            #pragma unroll
            for (int q = 0; q < 8; q++)
                acc2[q] = fma2(a2, dtou(w2d[j1*8 + q]), acc2[q]);
        }
        ull lg2[2] = {dtou(webd[0]), dtou(webd[1])};
        #pragma unroll
        for (int j2 = 0; j2 < 8; j2++){
            float2 f = unpack2(acc2[j2]);
            float ha = siluf(f.x), hb = siluf(f.y);
            int jj = 2*j2;
            ull ha2 = pack2(ha, ha), hb2 = pack2(hb, hb);
            lg2[0] = fma2(ha2, dtou(wed[jj*2+0]), lg2[0]);
            lg2[1] = fma2(ha2, dtou(wed[jj*2+1]), lg2[1]);
            lg2[0] = fma2(hb2, dtou(wed[(jj+1)*2+0]), lg2[0]);
            lg2[1] = fma2(hb2, dtou(wed[(jj+1)*2+1]), lg2[1]);
        }
        { float2 f = unpack2(lg2[0]); lg[j][0] = f.x; lg[j][1] = f.y; }
        { float2 f = unpack2(lg2[1]); lg[j][2] = f.x; lg[j][3] = f.y; }

        float2 bc2 = *(const float2*)&sC[kk*2];
        float c10 = siluf(fmaf(ts, cd0, bc2.x));
        float c11 = siluf(fmaf(ts, cd1, bc2.y));
        hcv0[j] = siluf(fmaf(c10, CP_SC2[0], fmaf(c11, CP_SC2[2], CP_SC2B[0])));
        hcv1[j] = siluf(fmaf(c10, CP_SC2[1], fmaf(c11, CP_SC2[3], CP_SC2B[1])));
    }

    float gm[4];
    #pragma unroll
    for (int h = 0; h < 4; h++){
        float m = lg[0][h];
        #pragma unroll
        for (int j = 1; j < 8; j++) m = fmaxf(m, lg[j][h]);
        #pragma unroll
        for (int o = 16; o > 0; o >>= 1)
            m = fmaxf(m, __shfl_xor_sync(0xffffffffu, m, o));
        gm[h] = m;
    }
    float inv[4];
    #pragma unroll
    for (int h = 0; h < 4; h++){
        float s = 0.f;
        #pragma unroll
        for (int j = 0; j < 8; j++){
            lg[j][h] = __expf(lg[j][h] - gm[h]);
            s += lg[j][h];
        }
        #pragma unroll
        for (int o = 16; o > 0; o >>= 1)
            s += __shfl_xor_sync(0xffffffffu, s, o);
        inv[h] = __fdividef(1.f, s);
    }

    float e8[8];
    #pragma unroll
    for (int i = 0; i < 8; i++) e8[i] = 0.f;
    #pragma unroll
    for (int h = 0; h < 4; h++){
        float* dst = attn_out + ((size_t)(b*4 + h)*TTc + t)*KKc + lane;
        #pragma unroll
        for (int j = 0; j < 8; j++){
            float a = lg[j][h] * inv[h];
            e8[h*2]   = fmaf(a, hcv0[j], e8[h*2]);
            e8[h*2+1] = fmaf(a, hcv1[j], e8[h*2+1]);
            dst[32*j] = a;
        }
    }
    #pragma unroll
    for (int i = 0; i < 8; i++){
        #pragma unroll
        for (int o = 16; o > 0; o >>= 1)
            e8[i] += __shfl_xor_sync(0xffffffffu, e8[i], o);
    }
    if (lane == 0){
        float* dst = g_ein + ((size_t)b*TTc + t)*8;
        *(float4*)dst       = *(float4*)&e8[0];
        *(float4*)(dst + 4) = *(float4*)&e8[4];
    }
}

// ---------------- launch ------------------------------------------------------
extern "C" void kernel_launch(void* const* d_in, const int* in_sizes, int n_in,
                              void* d_out, int out_size){
    const float* phs  = (const float*)d_in[0];
    const float* Wd   = (const float*)d_in[4];
    const float* bd   = (const float*)d_in[5];
    const float* W1   = (const float*)d_in[6];
    const float* b1   = (const float*)d_in[7];
    const float* W2   = (const float*)d_in[8];
    const float* b2   = (const float*)d_in[9];
    const float* W3   = (const float*)d_in[10];
    const float* b3   = (const float*)d_in[11];
    const float* wck  = (const float*)d_in[12];
    const float* wcb  = (const float*)d_in[13];
    const float* wlg  = (const float*)d_in[14];
    const float* wlb  = (const float*)d_in[15];
    const float* cck  = (const float*)d_in[16];
    const float* ccb  = (const float*)d_in[17];
    const float* clg  = (const float*)d_in[18];
    const float* clb  = (const float*)d_in[19];
    const float* sw1  = (const float*)d_in[20];
    const float* sw1b = (const float*)d_in[21];
    const float* sw2  = (const float*)d_in[22];
    const float* sw2b = (const float*)d_in[23];
    const float* sc1  = (const float*)d_in[24];
    const float* sc1b = (const float*)d_in[25];
    const float* sc2  = (const float*)d_in[26];
    const float* sc2b = (const float*)d_in[27];
    const float* weW  = (const float*)d_in[28];
    const float* web  = (const float*)d_in[29];
    const float* ceW  = (const float*)d_in[30];
    const float* ceb  = (const float*)d_in[31];
    (void)in_sizes; (void)n_in;

    float* outp = (float*)d_out;
    const size_t nOut  = (size_t)BB*TTc*DDc;
    const size_t nD    = (size_t)BB*KKc;
    const size_t nAttn = (size_t)BB*NHH*TTc*KKc;
    bool full = ((size_t)out_size >= nOut + nD + nAttn);

    float *vP, *oLP, *attnP, *dP, *bcatP, *WcatP, *cpackP;
    cudaGetSymbolAddress((void**)&vP,     g_v2);
    cudaGetSymbolAddress((void**)&oLP,    g_oL);
    cudaGetSymbolAddress((void**)&bcatP,  g_bcat);
    cudaGetSymbolAddress((void**)&WcatP,  g_Wcat);
    cudaGetSymbolAddress((void**)&cpackP, g_cpack);
    if (full){
        dP    = outp + nOut;
        attnP = outp + nOut + nD;
    } else {
        cudaGetSymbolAddress((void**)&dP,    g_dF);
        cudaGetSymbolAddress((void**)&attnP, g_attnF);
    }

    cudaFuncSetAttribute(mma_gemm<0>, cudaFuncAttributeMaxDynamicSharedMemorySize, MMA_SMEM);
    cudaFuncSetAttribute(mma_gemm<1>, cudaFuncAttributeMaxDynamicSharedMemorySize, MMA_SMEM);
    cudaFuncSetAttribute(mma_gemm<2>, cudaFuncAttributeMaxDynamicSharedMemorySize, MMA_SMEM);

    // prep + gather (blk 266), then ONE constant-bank upload
    k_pre<<<267, NV>>>(ceW, ceb, W3, b2, b3, W1, b1, wck, cck, Wd, bd,
                       sw1, sw2, sw2b, weW, web, sc1, sc2, sc2b);
    cudaMemcpyToSymbolAsync(c_pack, cpackP, 384*sizeof(float), 0,
                            cudaMemcpyDeviceToDevice);

    mma_gemm<0><<<dim3(BB*KKc/128, NV/64), 256, MMA_SMEM>>>(phs, WcatP, bcatP, vP);
    k_scan<<<BB, KKc>>>(dP);
    k_comb<<<BB*2, 128>>>(wcb, wlg, wlb, ccb, clg, clb, sw1, sw1b, sc1, sc1b);
    k_mlp<<<dim3(TTc/8, BB), 256>>>(attnP);
    mma_gemm<1><<<dim3(TTc/128, 1, BB*NHH), 256, MMA_SMEM>>>(attnP, vP, nullptr, oLP);
    mma_gemm<2><<<dim3(BB*TTc/128, DDc/64), 256, MMA_SMEM>>>(oLP, W2, nullptr, outp);
}